// round 9
// baseline (speedup 1.0000x reference)
#include <cuda_runtime.h>
#include <cuda_bf16.h>
#include <cstdint>

typedef __nv_bfloat16 bf16;

// ---------------- problem constants ----------------
#define DD 512
#define MAXB 32768
#define NSPLIT 16
#define BKT 64                          // K per stage -> 128B rows
#define MT 128
#define NT 64
#define TILE_A (MT * BKT * 2)           // 16384 B
#define TILE_BB (NT * BKT * 2)          // 8192 B
#define STAGE_B (2 * TILE_A + 2 * TILE_BB)  // 49152 B
#define SMEM_DYN (2 * STAGE_B + 128)        // 98432 B -> 2 CTAs/SM

// ---------------- scratch (device globals; no allocation) ----------------
__device__ __align__(256) bf16 g_s_hi[(size_t)MAXB * DD];
__device__ __align__(256) bf16 g_s_lo[(size_t)MAXB * DD];
__device__ __align__(256) bf16 g_p_hi[(size_t)MAXB * DD];
__device__ __align__(256) bf16 g_p_lo[(size_t)MAXB * DD];
__device__ __align__(256) bf16 g_st_hi[(size_t)DD * MAXB];
__device__ __align__(256) bf16 g_st_lo[(size_t)DD * MAXB];
__device__ __align__(256) bf16 g_pt_hi[(size_t)DD * MAXB];
__device__ __align__(256) bf16 g_pt_lo[(size_t)DD * MAXB];
__device__ __align__(256) bf16 g_wt_hi[DD * DD];
__device__ __align__(256) bf16 g_wt_lo[DD * DD];
__device__ __align__(256) bf16 g_wrt_hi[DD * DD];
__device__ __align__(256) bf16 g_wrt_lo[DD * DD];
__device__ __align__(256) float g_stim_out[(size_t)MAXB * DD];
__device__ __align__(256) float g_rec_out[(size_t)MAXB * DD];
__device__ __align__(256) float g_partS[(size_t)NSPLIT * DD * DD];
__device__ __align__(256) float g_partP[(size_t)NSPLIT * DD * DD];
__device__ __align__(256) float g_GS[DD * DD];
__device__ __align__(256) float g_GP[DD * DD];

// ---------------- PTX helpers (base-ISA only: sm_80+ safe) ----------------
__device__ __forceinline__ uint32_t smem_u32(const void* p) {
    uint32_t a;
    asm("{ .reg .u64 t; cvta.to.shared.u64 t, %1; cvt.u32.u64 %0, t; }" : "=r"(a) : "l"(p));
    return a;
}
__device__ __forceinline__ void ldsm_x4(uint32_t* r, uint32_t addr) {
    asm volatile("ldmatrix.sync.aligned.m8n8.x4.shared.b16 {%0,%1,%2,%3}, [%4];"
                 : "=r"(r[0]), "=r"(r[1]), "=r"(r[2]), "=r"(r[3]) : "r"(addr));
}
__device__ __forceinline__ void mma16816(float* c, const uint32_t* a, uint32_t b0, uint32_t b1) {
    asm volatile(
        "mma.sync.aligned.m16n8k16.row.col.f32.bf16.bf16.f32 "
        "{%0,%1,%2,%3}, {%4,%5,%6,%7}, {%8,%9}, {%0,%1,%2,%3};"
        : "+f"(c[0]), "+f"(c[1]), "+f"(c[2]), "+f"(c[3])
        : "r"(a[0]), "r"(a[1]), "r"(a[2]), "r"(a[3]), "r"(b0), "r"(b1));
}
__device__ __forceinline__ void cp16(uint32_t dst, const void* src) {
    asm volatile("cp.async.cg.shared.global [%0], [%1], 16;" :: "r"(dst), "l"(src) : "memory");
}
#define CP_COMMIT() asm volatile("cp.async.commit_group;" ::: "memory")

// swizzled smem byte offset within a tile: 128B rows, 8 x 16B chunks, chunk xor (row&7)
__device__ __forceinline__ uint32_t swz(int row, int chunk) {
    return (uint32_t)(row * 128 + ((chunk ^ (row & 7)) << 4));
}

__device__ __forceinline__ uint32_t pack2(bf16 a, bf16 b) {
    return (uint32_t)__bfloat16_as_ushort(a) | ((uint32_t)__bfloat16_as_ushort(b) << 16);
}

// ---------------- segment descriptor for the merged GEMM launch ----------------
struct Seg {
    const bf16 *Ah, *Al, *Bh, *Bl;
    int lda, ldb;
    float* C;
    int pstride;
    int kc;     // K per block
    int gram;   // 0: forward tiling, 1: upper-tri gram tiling
    int blk0;   // first global block id of this segment
};
struct Seg4 { Seg s[4]; };

// ---------------- merged mma.sync GEMM: all 4 GEMMs in one launch ----------------
__global__ __launch_bounds__(256, 2)
void mma_all(Seg4 segs) {
    extern __shared__ char smraw[];
    const uint32_t base = (smem_u32(smraw) + 127u) & ~127u;

    const int bid = blockIdx.x;
    int si = (bid >= segs.s[2].blk0) ? ((bid >= segs.s[3].blk0) ? 3 : 2)
                                     : ((bid >= segs.s[1].blk0) ? 1 : 0);
    const Seg sg = segs.s[si];
    const int b = bid - sg.blk0;

    const int tid = threadIdx.x;
    const int lane = tid & 31;
    const int wid = tid >> 5;
    const int wm = wid >> 1;       // 4 warp-rows of 32
    const int wn = wid & 1;        // 2 warp-cols of 32
    const int r15 = lane & 15;
    const int hi4 = lane >> 4;

    int m0, n0, kbase;
    float* C = sg.C;
    if (sg.gram) {
        // 20 upper-tri (128-granular) tiles of shape 128x64
        const int PI[20] = {0,0, 0,0, 0,0, 0,0, 1,1, 1,1, 1,1, 2,2, 2,2, 3,3};
        const int PN[20] = {0,1, 2,3, 4,5, 6,7, 2,3, 4,5, 6,7, 4,5, 6,7, 6,7};
        int p = b % 20, z = b / 20;
        m0 = PI[p] * MT;
        n0 = PN[p] * NT;
        kbase = z * sg.kc;
        C += (long)z * sg.pstride;
    } else {
        m0 = (b >> 3) * MT;
        n0 = (b & 7) * NT;
        kbase = 0;
    }
    const int niter = sg.kc / BKT;

    // ---- hoisted loader state (all int32 math; pointers advance per stage) ----
    const int rr = tid >> 3;                 // 0..31 base row
    const int cch = tid & 7;                 // chunk index
    const uint32_t dA = (uint32_t)(rr * 128 + ((cch ^ (rr & 7)) << 4));
    const int offA = 32 * sg.lda;            // per-q source row step (elements)
    const int offB = 32 * sg.ldb;
    const bf16* pAh = sg.Ah + (m0 + rr) * sg.lda + cch * 8 + kbase;
    const bf16* pAl = sg.Al + (m0 + rr) * sg.lda + cch * 8 + kbase;
    const bf16* pBh = sg.Bh + (n0 + rr) * sg.ldb + cch * 8 + kbase;
    const bf16* pBl = sg.Bl + (n0 + rr) * sg.ldb + cch * 8 + kbase;

#define LOAD_STAGE(sbase) do {                                                  \
    const uint32_t d0 = (sbase) + dA;                                           \
    _Pragma("unroll") for (int q = 0; q < 4; ++q)                               \
        cp16(d0 + q * 4096, pAh + q * offA);                                    \
    _Pragma("unroll") for (int q = 0; q < 4; ++q)                               \
        cp16(d0 + TILE_A + q * 4096, pAl + q * offA);                           \
    _Pragma("unroll") for (int q = 0; q < 2; ++q)                               \
        cp16(d0 + 2 * TILE_A + q * 4096, pBh + q * offB);                       \
    _Pragma("unroll") for (int q = 0; q < 2; ++q)                               \
        cp16(d0 + 2 * TILE_A + TILE_BB + q * 4096, pBl + q * offB);             \
    CP_COMMIT();                                                                \
    pAh += BKT; pAl += BKT; pBh += BKT; pBl += BKT;                             \
} while (0)

    float acc[2][4][4];
#pragma unroll
    for (int i = 0; i < 2; ++i)
#pragma unroll
        for (int j = 0; j < 4; ++j)
#pragma unroll
            for (int q = 0; q < 4; ++q) acc[i][j][q] = 0.f;

    // prologue: stage 0
    LOAD_STAGE(base);

    for (int i = 0; i < niter; ++i) {
        asm volatile("cp.async.wait_group 0;" ::: "memory");
        __syncthreads();

        if (i + 1 < niter)
            LOAD_STAGE(base + ((i + 1) & 1) * STAGE_B);

        const uint32_t sb = base + (i & 1) * STAGE_B;
        const uint32_t Ah = sb, Al = sb + TILE_A;
        const uint32_t Bh = sb + 2 * TILE_A, Bl = sb + 2 * TILE_A + TILE_BB;

#pragma unroll
        for (int ks = 0; ks < 4; ++ks) {
            uint32_t ah[2][4], al[2][4], bh[2][4], bl[2][4];
            int ck = 2 * ks + hi4;
#pragma unroll
            for (int mt = 0; mt < 2; ++mt) {
                int row = wm * 32 + mt * 16 + r15;
                ldsm_x4(ah[mt], Ah + swz(row, ck));
                ldsm_x4(al[mt], Al + swz(row, ck));
            }
#pragma unroll
            for (int np = 0; np < 2; ++np) {
                int row = wn * 32 + np * 16 + r15;
                ldsm_x4(bh[np], Bh + swz(row, ck));
                ldsm_x4(bl[np], Bl + swz(row, ck));
            }
#pragma unroll
            for (int mt = 0; mt < 2; ++mt)
#pragma unroll
                for (int nt = 0; nt < 4; ++nt) {
                    int np = nt >> 1, p = nt & 1;
                    mma16816(acc[mt][nt], ah[mt], bh[np][p], bh[np][p + 2]);
                    mma16816(acc[mt][nt], ah[mt], bl[np][p], bl[np][p + 2]);
                    mma16816(acc[mt][nt], al[mt], bh[np][p], bh[np][p + 2]);
                }
        }
    }

    // epilogue: write fp32 directly from accumulators
#pragma unroll
    for (int mt = 0; mt < 2; ++mt) {
        int row = m0 + wm * 32 + mt * 16 + (lane >> 2);
#pragma unroll
        for (int nt = 0; nt < 4; ++nt) {
            int col = n0 + wn * 32 + nt * 8 + 2 * (lane & 3);
            *(float2*)&C[(long)row * DD + col] = make_float2(acc[mt][nt][0], acc[mt][nt][1]);
            *(float2*)&C[(long)(row + 8) * DD + col] = make_float2(acc[mt][nt][2], acc[mt][nt][3]);
        }
    }
#undef LOAD_STAGE
}

// ------- prep: fully-coalesced hi/lo split, row-major + transposed, packed stores -------
__global__ __launch_bounds__(256) void prep_big(const float* __restrict__ X,
                                                uint32_t* __restrict__ Hr, uint32_t* __restrict__ Lr,
                                                uint32_t* __restrict__ Th, uint32_t* __restrict__ Tl,
                                                int R, int C) {
    __shared__ float s[64][65];
    const int tid = threadIdx.x;
    const int c0 = blockIdx.x * 64, r0 = blockIdx.y * 64;

#pragma unroll
    for (int k = 0; k < 8; ++k) {
        int u = tid + k * 256;
        int rl = u >> 5, c2 = (u & 31) * 2;
        long ga = (long)(r0 + rl) * C + c0 + c2;
        float2 v = *(const float2*)&X[ga];
        bf16 h0 = __float2bfloat16(v.x);
        bf16 l0 = __float2bfloat16(v.x - __bfloat162float(h0));
        bf16 h1 = __float2bfloat16(v.y);
        bf16 l1 = __float2bfloat16(v.y - __bfloat162float(h1));
        Hr[ga >> 1] = pack2(h0, h1);
        Lr[ga >> 1] = pack2(l0, l1);
        s[c2][rl] = v.x;
        s[c2 + 1][rl] = v.y;
    }
    __syncthreads();
#pragma unroll
    for (int k = 0; k < 8; ++k) {
        int u = tid + k * 256;
        int fl = u >> 5, r2 = (u & 31) * 2;
        float v0 = s[fl][r2], v1 = s[fl][r2 + 1];
        bf16 h0 = __float2bfloat16(v0);
        bf16 l0 = __float2bfloat16(v0 - __bfloat162float(h0));
        bf16 h1 = __float2bfloat16(v1);
        bf16 l1 = __float2bfloat16(v1 - __bfloat162float(h1));
        long ta = (long)(c0 + fl) * R + r0 + r2;
        Th[ta >> 1] = pack2(h0, h1);
        Tl[ta >> 1] = pack2(l0, l1);
    }
}

// ------- prep for weights: transposed-only split, W and Wr via grid.z -------
__global__ __launch_bounds__(256) void prep_w(const float* __restrict__ W0,
                                              const float* __restrict__ W1,
                                              uint32_t* __restrict__ T0h, uint32_t* __restrict__ T0l,
                                              uint32_t* __restrict__ T1h, uint32_t* __restrict__ T1l) {
    __shared__ float s[64][65];
    const int tid = threadIdx.x;
    const int c0 = blockIdx.x * 64, r0 = blockIdx.y * 64;
    const float* X = blockIdx.z ? W1 : W0;
    uint32_t* Th = blockIdx.z ? T1h : T0h;
    uint32_t* Tl = blockIdx.z ? T1l : T0l;

#pragma unroll
    for (int k = 0; k < 8; ++k) {
        int u = tid + k * 256;
        int rl = u >> 5, c2 = (u & 31) * 2;
        float2 v = *(const float2*)&X[(long)(r0 + rl) * DD + c0 + c2];
        s[c2][rl] = v.x;
        s[c2 + 1][rl] = v.y;
    }
    __syncthreads();
#pragma unroll
    for (int k = 0; k < 8; ++k) {
        int u = tid + k * 256;
        int fl = u >> 5, r2 = (u & 31) * 2;
        float v0 = s[fl][r2], v1 = s[fl][r2 + 1];
        bf16 h0 = __float2bfloat16(v0);
        bf16 l0 = __float2bfloat16(v0 - __bfloat162float(h0));
        bf16 h1 = __float2bfloat16(v1);
        bf16 l1 = __float2bfloat16(v1 - __bfloat162float(h1));
        long ta = (long)(c0 + fl) * DD + r0 + r2;
        Th[ta >> 1] = pack2(h0, h1);
        Tl[ta >> 1] = pack2(l0, l1);
    }
}

// ---------------- reduce split-K Gram partials (symmetric mirror, 128-granular) ----------------
__global__ void reduce_gram() {
    int idx = blockIdx.x * blockDim.x + threadIdx.x;
    int i = idx >> 9, j = idx & 511;
    size_t src = ((i >> 7) <= (j >> 7)) ? ((size_t)i * DD + j) : ((size_t)j * DD + i);
    float s = 0.f, p = 0.f;
#pragma unroll 8
    for (int z = 0; z < NSPLIT; ++z) {
        s += g_partS[(size_t)z * DD * DD + src];
        p += g_partP[(size_t)z * DD * DD + src];
    }
    g_GS[idx] = s;
    g_GP[idx] = p;
}

// ---------------- warp-per-row fused LN(rec) -> add stim -> relu -> LN(act) ----------------
__global__ __launch_bounds__(256) void ln_fuse(const float* __restrict__ rec,
                                               const float* __restrict__ stim,
                                               const float* __restrict__ grec,
                                               const float* __restrict__ brec,
                                               const float* __restrict__ gact,
                                               const float* __restrict__ bact,
                                               float* __restrict__ out) {
    const int lane = threadIdx.x & 31;
    const long row = (long)blockIdx.x * 8 + (threadIdx.x >> 5);
    const float* rr = rec + row * DD;
    const float* sr = stim + row * DD;
    float* orow = out + row * DD;

    float x[16];
    float a = 0.f, bsum = 0.f;
#pragma unroll
    for (int e = 0; e < 16; ++e) {
        x[e] = rr[e * 32 + lane];
        a += x[e];
        bsum += x[e] * x[e];
    }
#pragma unroll
    for (int o = 16; o; o >>= 1) {
        a += __shfl_xor_sync(0xffffffffu, a, o);
        bsum += __shfl_xor_sync(0xffffffffu, bsum, o);
    }
    float mu = a * (1.f / DD);
    float var = bsum * (1.f / DD) - mu * mu;
    float rstd = rsqrtf(var + 1e-5f);

    float v[16];
    a = 0.f; bsum = 0.f;
#pragma unroll
    for (int e = 0; e < 16; ++e) {
        int c = e * 32 + lane;
        float rn = (x[e] - mu) * rstd * grec[c] + brec[c];
        v[e] = fmaxf(sr[c] + rn, 0.f);
        a += v[e];
        bsum += v[e] * v[e];
    }
#pragma unroll
    for (int o = 16; o; o >>= 1) {
        a += __shfl_xor_sync(0xffffffffu, a, o);
        bsum += __shfl_xor_sync(0xffffffffu, bsum, o);
    }
    float mu2 = a * (1.f / DD);
    float var2 = bsum * (1.f / DD) - mu2 * mu2;
    float rstd2 = rsqrtf(var2 + 1e-5f);
#pragma unroll
    for (int e = 0; e < 16; ++e) {
        int c = e * 32 + lane;
        orow[c] = (v[e] - mu2) * rstd2 * gact[c] + bact[c];
    }
}

// ---------- weight update: out = l2norm_rows(W*(1-decay_i) + alpha_j*(G@W)), both mats ----------
#define RPC 8
__global__ __launch_bounds__(512) void weight_update(const float* __restrict__ W0,
                                                     const float* __restrict__ G0,
                                                     const float* __restrict__ W1,
                                                     const float* __restrict__ G1,
                                                     const float* __restrict__ alpha,
                                                     const float* __restrict__ decay,
                                                     float* __restrict__ out0,
                                                     float* __restrict__ out1) {
    const float* Wm = blockIdx.y ? W1 : W0;
    const float* G = blockIdx.y ? G1 : G0;
    float* outp = blockIdx.y ? out1 : out0;

    const int i0 = blockIdx.x * RPC;
    const int j = threadIdx.x;
    const int lane = j & 31;
    const int w = j >> 5;

    __shared__ float Gsm[RPC][DD];
    __shared__ float red[16];
    __shared__ float norms[RPC];

#pragma unroll
    for (int r = 0; r < RPC; ++r) Gsm[r][j] = G[(size_t)(i0 + r) * DD + j];
    __syncthreads();

    float acc[RPC];
#pragma unroll
    for (int r = 0; r < RPC; ++r) acc[r] = 0.f;

#pragma unroll 4
    for (int k = 0; k < DD; ++k) {
        float wv = Wm[(size_t)k * DD + j];
#pragma unroll
        for (int r = 0; r < RPC; ++r) acc[r] = fmaf(Gsm[r][k], wv, acc[r]);
    }

    float aj = alpha[j];
#pragma unroll
    for (int r = 0; r < RPC; ++r)
        acc[r] = Wm[(size_t)(i0 + r) * DD + j] * (1.f - decay[i0 + r]) + aj * acc[r];

    for (int r = 0; r < RPC; ++r) {
        float s = acc[r] * acc[r];
#pragma unroll
        for (int o = 16; o; o >>= 1) s += __shfl_xor_sync(0xffffffffu, s, o);
        if (lane == 0) red[w] = s;
        __syncthreads();
        if (j == 0) {
            float tsum = 0.f;
#pragma unroll
            for (int q = 0; q < 16; ++q) tsum += red[q];
            norms[r] = fmaxf(sqrtf(tsum), 1e-12f);
        }
        __syncthreads();
    }

#pragma unroll
    for (int r = 0; r < RPC; ++r)
        outp[(size_t)(i0 + r) * DD + j] = acc[r] / norms[r];
}

// ---------------- launch ----------------
extern "C" void kernel_launch(void* const* d_in, const int* in_sizes, int n_in,
                              void* d_out, int out_size) {
    const float* stim = (const float*)d_in[0];
    const float* prev = (const float*)d_in[1];
    const float* W    = (const float*)d_in[2];
    const float* Wr   = (const float*)d_in[3];
    const float* alpha = (const float*)d_in[4];
    const float* decay = (const float*)d_in[5];
    const float* gact = (const float*)d_in[6];
    const float* bact = (const float*)d_in[7];
    const float* grec = (const float*)d_in[8];
    const float* brec = (const float*)d_in[9];
    float* out = (float*)d_out;

    const int Brows = in_sizes[0] / DD;  // 32768

    bf16 *s_hi, *s_lo, *p_hi, *p_lo, *st_hi, *st_lo, *pt_hi, *pt_lo;
    bf16 *wt_hi, *wt_lo, *wrt_hi, *wrt_lo;
    float *stim_out, *rec_out, *partS, *partP, *GS, *GP;
    cudaGetSymbolAddress((void**)&s_hi, g_s_hi);
    cudaGetSymbolAddress((void**)&s_lo, g_s_lo);
    cudaGetSymbolAddress((void**)&p_hi, g_p_hi);
    cudaGetSymbolAddress((void**)&p_lo, g_p_lo);
    cudaGetSymbolAddress((void**)&st_hi, g_st_hi);
    cudaGetSymbolAddress((void**)&st_lo, g_st_lo);
    cudaGetSymbolAddress((void**)&pt_hi, g_pt_hi);
    cudaGetSymbolAddress((void**)&pt_lo, g_pt_lo);
    cudaGetSymbolAddress((void**)&wt_hi, g_wt_hi);
    cudaGetSymbolAddress((void**)&wt_lo, g_wt_lo);
    cudaGetSymbolAddress((void**)&wrt_hi, g_wrt_hi);
    cudaGetSymbolAddress((void**)&wrt_lo, g_wrt_lo);
    cudaGetSymbolAddress((void**)&stim_out, g_stim_out);
    cudaGetSymbolAddress((void**)&rec_out, g_rec_out);
    cudaGetSymbolAddress((void**)&partS, g_partS);
    cudaGetSymbolAddress((void**)&partP, g_partP);
    cudaGetSymbolAddress((void**)&GS, g_GS);
    cudaGetSymbolAddress((void**)&GP, g_GP);

    cudaFuncSetAttribute(mma_all, cudaFuncAttributeMaxDynamicSharedMemorySize, SMEM_DYN);

    // launches 0-2: prep (mma_all stays at ncu capture index 3)
    prep_big<<<dim3(DD / 64, Brows / 64), 256>>>(stim, (uint32_t*)s_hi, (uint32_t*)s_lo,
                                                 (uint32_t*)st_hi, (uint32_t*)st_lo, Brows, DD);
    prep_big<<<dim3(DD / 64, Brows / 64), 256>>>(prev, (uint32_t*)p_hi, (uint32_t*)p_lo,
                                                 (uint32_t*)pt_hi, (uint32_t*)pt_lo, Brows, DD);
    prep_w<<<dim3(DD / 64, DD / 64, 2), 256>>>(W, Wr, (uint32_t*)wt_hi, (uint32_t*)wt_lo,
                                               (uint32_t*)wrt_hi, (uint32_t*)wrt_lo);

    // launch 3: ALL four GEMMs merged, gram blocks first (LPT order)
    const int fwdBlocks = (Brows / MT) * (DD / NT);   // 2048
    const int gramBlocks = 20 * NSPLIT;               // 320
    const int kcg = Brows / NSPLIT;                   // 2048
    Seg4 segs;
    segs.s[0] = {st_hi, st_lo, st_hi, st_lo, Brows, Brows, partS, DD * DD, kcg, 1, 0};
    segs.s[1] = {pt_hi, pt_lo, pt_hi, pt_lo, Brows, Brows, partP, DD * DD, kcg, 1, gramBlocks};
    segs.s[2] = {s_hi, s_lo, wt_hi, wt_lo, DD, DD, stim_out, 0, DD, 0, 2 * gramBlocks};
    segs.s[3] = {p_hi, p_lo, wrt_hi, wrt_lo, DD, DD, rec_out, 0, DD, 0, 2 * gramBlocks + fwdBlocks};
    mma_all<<<2 * gramBlocks + 2 * fwdBlocks, 256, SMEM_DYN>>>(segs);

    reduce_gram<<<(DD * DD) / 256, 256>>>();

    ln_fuse<<<(unsigned)(Brows / 8), 256>>>(rec_out, stim_out, grec, brec, gact, bact, out);

    size_t off = (size_t)Brows * DD;
    weight_update<<<dim3(DD / RPC, 2), 512>>>(W, GS, Wr, GP, alpha, decay,
                                              out + off, out + off + (size_t)DD * DD);
}

// round 10
// speedup vs baseline: 1.2107x; 1.2107x over previous
#include <cuda_runtime.h>
#include <cuda_fp16.h>
#include <cstdint>

typedef __half fp16;

// ---------------- problem constants ----------------
#define DD 512
#define MAXB 32768
#define NSPLIT 16
#define BKT 64                          // K per stage -> 128B rows
#define MT 128
#define NT 64
#define TILE_A (MT * BKT * 2)           // 16384 B
#define TILE_BH (NT * BKT * 2)          // 8192 B
#define STAGE_B (2 * TILE_A + TILE_BH)  // 40960 B (Ahi, Alo, Bhi)
#define SMEM_DYN (2 * STAGE_B + 128)    // 82048 B -> 2 CTAs/SM

// ---------------- scratch (device globals; no allocation) ----------------
__device__ __align__(256) fp16 g_s_hi[(size_t)MAXB * DD];
__device__ __align__(256) fp16 g_s_lo[(size_t)MAXB * DD];
__device__ __align__(256) fp16 g_p_hi[(size_t)MAXB * DD];
__device__ __align__(256) fp16 g_p_lo[(size_t)MAXB * DD];
__device__ __align__(256) fp16 g_st_hi[(size_t)DD * MAXB];
__device__ __align__(256) fp16 g_st_lo[(size_t)DD * MAXB];
__device__ __align__(256) fp16 g_pt_hi[(size_t)DD * MAXB];
__device__ __align__(256) fp16 g_pt_lo[(size_t)DD * MAXB];
__device__ __align__(256) fp16 g_wt_hi[DD * DD];
__device__ __align__(256) fp16 g_wrt_hi[DD * DD];
__device__ __align__(256) float g_stim_out[(size_t)MAXB * DD];
__device__ __align__(256) float g_rec_out[(size_t)MAXB * DD];
__device__ __align__(256) float g_partS[(size_t)NSPLIT * DD * DD];
__device__ __align__(256) float g_partP[(size_t)NSPLIT * DD * DD];
__device__ __align__(256) float g_GS[DD * DD];
__device__ __align__(256) float g_GP[DD * DD];

// ---------------- PTX helpers (base-ISA only: sm_80+ safe) ----------------
__device__ __forceinline__ uint32_t smem_u32(const void* p) {
    uint32_t a;
    asm("{ .reg .u64 t; cvta.to.shared.u64 t, %1; cvt.u32.u64 %0, t; }" : "=r"(a) : "l"(p));
    return a;
}
__device__ __forceinline__ void ldsm_x4(uint32_t* r, uint32_t addr) {
    asm volatile("ldmatrix.sync.aligned.m8n8.x4.shared.b16 {%0,%1,%2,%3}, [%4];"
                 : "=r"(r[0]), "=r"(r[1]), "=r"(r[2]), "=r"(r[3]) : "r"(addr));
}
__device__ __forceinline__ void mma16816(float* c, const uint32_t* a, uint32_t b0, uint32_t b1) {
    asm volatile(
        "mma.sync.aligned.m16n8k16.row.col.f32.f16.f16.f32 "
        "{%0,%1,%2,%3}, {%4,%5,%6,%7}, {%8,%9}, {%0,%1,%2,%3};"
        : "+f"(c[0]), "+f"(c[1]), "+f"(c[2]), "+f"(c[3])
        : "r"(a[0]), "r"(a[1]), "r"(a[2]), "r"(a[3]), "r"(b0), "r"(b1));
}
__device__ __forceinline__ void cp16(uint32_t dst, const void* src) {
    asm volatile("cp.async.cg.shared.global [%0], [%1], 16;" :: "r"(dst), "l"(src) : "memory");
}
#define CP_COMMIT() asm volatile("cp.async.commit_group;" ::: "memory")

// swizzled smem byte offset within a tile: 128B rows, 8 x 16B chunks, chunk xor (row&7)
__device__ __forceinline__ uint32_t swz(int row, int chunk) {
    return (uint32_t)(row * 128 + ((chunk ^ (row & 7)) << 4));
}

__device__ __forceinline__ uint32_t pack2h(fp16 a, fp16 b) {
    return (uint32_t)__half_as_ushort(a) | ((uint32_t)__half_as_ushort(b) << 16);
}

// ---------------- segment descriptor for the merged GEMM launch ----------------
struct Seg {
    const fp16 *Ah, *Al, *Bh;
    int lda, ldb;
    float* C;
    int pstride;
    int kc;     // K per block
    int gram;   // 0: forward tiling, 1: upper-tri gram tiling
    int blk0;   // first global block id of this segment
};
struct Seg4 { Seg s[4]; };

// ---------------- merged mma.sync GEMM: all 4 GEMMs in one launch ----------------
// C = A @ B^T with A = Ahi + Alo (fp16 pair), B = Bhi (fp16).
// Exact identity: (hi_a + lo_a) * hi_b = x_a * hi_b; dropped term x_a*lo_b ~ 2.8e-4 rel.
__global__ __launch_bounds__(256, 2)
void mma_all(Seg4 segs) {
    extern __shared__ char smraw[];
    const uint32_t base = (smem_u32(smraw) + 127u) & ~127u;

    const int bid = blockIdx.x;
    int si = (bid >= segs.s[2].blk0) ? ((bid >= segs.s[3].blk0) ? 3 : 2)
                                     : ((bid >= segs.s[1].blk0) ? 1 : 0);
    const Seg sg = segs.s[si];
    const int b = bid - sg.blk0;

    const int tid = threadIdx.x;
    const int lane = tid & 31;
    const int wid = tid >> 5;
    const int wm = wid >> 1;       // 4 warp-rows of 32
    const int wn = wid & 1;        // 2 warp-cols of 32
    const int r15 = lane & 15;
    const int hi4 = lane >> 4;

    int m0, n0, kbase;
    float* C = sg.C;
    if (sg.gram) {
        // 20 upper-tri (128-granular) tiles of shape 128x64
        const int PI[20] = {0,0, 0,0, 0,0, 0,0, 1,1, 1,1, 1,1, 2,2, 2,2, 3,3};
        const int PN[20] = {0,1, 2,3, 4,5, 6,7, 2,3, 4,5, 6,7, 4,5, 6,7, 6,7};
        int p = b % 20, z = b / 20;
        m0 = PI[p] * MT;
        n0 = PN[p] * NT;
        kbase = z * sg.kc;
        C += (long)z * sg.pstride;
    } else {
        m0 = (b >> 3) * MT;
        n0 = (b & 7) * NT;
        kbase = 0;
    }
    const int niter = sg.kc / BKT;

    // ---- hoisted loader state (int32 math; pointers advance per stage) ----
    const int rr = tid >> 3;                 // 0..31 base row
    const int cch = tid & 7;                 // chunk index
    const uint32_t dA = (uint32_t)(rr * 128 + ((cch ^ (rr & 7)) << 4));
    const int offA = 32 * sg.lda;
    const int offB = 32 * sg.ldb;
    const fp16* pAh = sg.Ah + (m0 + rr) * sg.lda + cch * 8 + kbase;
    const fp16* pAl = sg.Al + (m0 + rr) * sg.lda + cch * 8 + kbase;
    const fp16* pBh = sg.Bh + (n0 + rr) * sg.ldb + cch * 8 + kbase;

#define LOAD_STAGE(sbase) do {                                                  \
    const uint32_t d0 = (sbase) + dA;                                           \
    _Pragma("unroll") for (int q = 0; q < 4; ++q)                               \
        cp16(d0 + q * 4096, pAh + q * offA);                                    \
    _Pragma("unroll") for (int q = 0; q < 4; ++q)                               \
        cp16(d0 + TILE_A + q * 4096, pAl + q * offA);                           \
    _Pragma("unroll") for (int q = 0; q < 2; ++q)                               \
        cp16(d0 + 2 * TILE_A + q * 4096, pBh + q * offB);                       \
    CP_COMMIT();                                                                \
    pAh += BKT; pAl += BKT; pBh += BKT;                                         \
} while (0)

    float acc[2][4][4];
#pragma unroll
    for (int i = 0; i < 2; ++i)
#pragma unroll
        for (int j = 0; j < 4; ++j)
#pragma unroll
            for (int q = 0; q < 4; ++q) acc[i][j][q] = 0.f;

    // prologue: stage 0
    LOAD_STAGE(base);

    for (int i = 0; i < niter; ++i) {
        asm volatile("cp.async.wait_group 0;" ::: "memory");
        __syncthreads();

        if (i + 1 < niter)
            LOAD_STAGE(base + ((i + 1) & 1) * STAGE_B);

        const uint32_t sb = base + (i & 1) * STAGE_B;
        const uint32_t Ah = sb, Al = sb + TILE_A, Bh = sb + 2 * TILE_A;

#pragma unroll
        for (int ks = 0; ks < 4; ++ks) {
            uint32_t ah[2][4], al[2][4], bh[2][4];
            int ck = 2 * ks + hi4;
#pragma unroll
            for (int mt = 0; mt < 2; ++mt) {
                int row = wm * 32 + mt * 16 + r15;
                ldsm_x4(ah[mt], Ah + swz(row, ck));
                ldsm_x4(al[mt], Al + swz(row, ck));
            }
#pragma unroll
            for (int np = 0; np < 2; ++np) {
                int row = wn * 32 + np * 16 + r15;
                ldsm_x4(bh[np], Bh + swz(row, ck));
            }
#pragma unroll
            for (int mt = 0; mt < 2; ++mt)
#pragma unroll
                for (int nt = 0; nt < 4; ++nt) {
                    int np = nt >> 1, p = nt & 1;
                    mma16816(acc[mt][nt], ah[mt], bh[np][p], bh[np][p + 2]);
                    mma16816(acc[mt][nt], al[mt], bh[np][p], bh[np][p + 2]);
                }
        }
    }

    // epilogue: write fp32 directly from accumulators
#pragma unroll
    for (int mt = 0; mt < 2; ++mt) {
        int row = m0 + wm * 32 + mt * 16 + (lane >> 2);
#pragma unroll
        for (int nt = 0; nt < 4; ++nt) {
            int col = n0 + wn * 32 + nt * 8 + 2 * (lane & 3);
            *(float2*)&C[(long)row * DD + col] = make_float2(acc[mt][nt][0], acc[mt][nt][1]);
            *(float2*)&C[(long)(row + 8) * DD + col] = make_float2(acc[mt][nt][2], acc[mt][nt][3]);
        }
    }
#undef LOAD_STAGE
}

// ------- prep: coalesced fp16 hi/lo split, row-major + transposed, packed stores -------
__global__ __launch_bounds__(256) void prep_big(const float* __restrict__ X,
                                                uint32_t* __restrict__ Hr, uint32_t* __restrict__ Lr,
                                                uint32_t* __restrict__ Th, uint32_t* __restrict__ Tl,
                                                int R, int C) {
    __shared__ float s[64][65];
    const int tid = threadIdx.x;
    const int c0 = blockIdx.x * 64, r0 = blockIdx.y * 64;

#pragma unroll
    for (int k = 0; k < 8; ++k) {
        int u = tid + k * 256;
        int rl = u >> 5, c2 = (u & 31) * 2;
        long ga = (long)(r0 + rl) * C + c0 + c2;
        float2 v = *(const float2*)&X[ga];
        fp16 h0 = __float2half(v.x);
        fp16 l0 = __float2half(v.x - __half2float(h0));
        fp16 h1 = __float2half(v.y);
        fp16 l1 = __float2half(v.y - __half2float(h1));
        Hr[ga >> 1] = pack2h(h0, h1);
        Lr[ga >> 1] = pack2h(l0, l1);
        s[c2][rl] = v.x;
        s[c2 + 1][rl] = v.y;
    }
    __syncthreads();
#pragma unroll
    for (int k = 0; k < 8; ++k) {
        int u = tid + k * 256;
        int fl = u >> 5, r2 = (u & 31) * 2;
        float v0 = s[fl][r2], v1 = s[fl][r2 + 1];
        fp16 h0 = __float2half(v0);
        fp16 l0 = __float2half(v0 - __half2float(h0));
        fp16 h1 = __float2half(v1);
        fp16 l1 = __float2half(v1 - __half2float(h1));
        long ta = (long)(c0 + fl) * R + r0 + r2;
        Th[ta >> 1] = pack2h(h0, h1);
        Tl[ta >> 1] = pack2h(l0, l1);
    }
}

// ------- prep for weights: transposed HI-only (B operand never needs lo) -------
__global__ __launch_bounds__(256) void prep_w(const float* __restrict__ W0,
                                              const float* __restrict__ W1,
                                              uint32_t* __restrict__ T0h,
                                              uint32_t* __restrict__ T1h) {
    __shared__ float s[64][65];
    const int tid = threadIdx.x;
    const int c0 = blockIdx.x * 64, r0 = blockIdx.y * 64;
    const float* X = blockIdx.z ? W1 : W0;
    uint32_t* Th = blockIdx.z ? T1h : T0h;

#pragma unroll
    for (int k = 0; k < 8; ++k) {
        int u = tid + k * 256;
        int rl = u >> 5, c2 = (u & 31) * 2;
        float2 v = *(const float2*)&X[(long)(r0 + rl) * DD + c0 + c2];
        s[c2][rl] = v.x;
        s[c2 + 1][rl] = v.y;
    }
    __syncthreads();
#pragma unroll
    for (int k = 0; k < 8; ++k) {
        int u = tid + k * 256;
        int fl = u >> 5, r2 = (u & 31) * 2;
        fp16 h0 = __float2half(s[fl][r2]);
        fp16 h1 = __float2half(s[fl][r2 + 1]);
        long ta = (long)(c0 + fl) * DD + r0 + r2;
        Th[ta >> 1] = pack2h(h0, h1);
    }
}

// ---------------- reduce split-K Gram partials (symmetric mirror, 128-granular) ----------------
__global__ void reduce_gram() {
    int idx = blockIdx.x * blockDim.x + threadIdx.x;
    int i = idx >> 9, j = idx & 511;
    size_t src = ((i >> 7) <= (j >> 7)) ? ((size_t)i * DD + j) : ((size_t)j * DD + i);
    float s = 0.f, p = 0.f;
#pragma unroll 8
    for (int z = 0; z < NSPLIT; ++z) {
        s += g_partS[(size_t)z * DD * DD + src];
        p += g_partP[(size_t)z * DD * DD + src];
    }
    g_GS[idx] = s;
    g_GP[idx] = p;
}

// ---------------- warp-per-row fused LN(rec) -> add stim -> relu -> LN(act) ----------------
__global__ __launch_bounds__(256) void ln_fuse(const float* __restrict__ rec,
                                               const float* __restrict__ stim,
                                               const float* __restrict__ grec,
                                               const float* __restrict__ brec,
                                               const float* __restrict__ gact,
                                               const float* __restrict__ bact,
                                               float* __restrict__ out) {
    const int lane = threadIdx.x & 31;
    const long row = (long)blockIdx.x * 8 + (threadIdx.x >> 5);
    const float* rr = rec + row * DD;
    const float* sr = stim + row * DD;
    float* orow = out + row * DD;

    float x[16];
    float a = 0.f, bsum = 0.f;
#pragma unroll
    for (int e = 0; e < 16; ++e) {
        x[e] = rr[e * 32 + lane];
        a += x[e];
        bsum += x[e] * x[e];
    }
#pragma unroll
    for (int o = 16; o; o >>= 1) {
        a += __shfl_xor_sync(0xffffffffu, a, o);
        bsum += __shfl_xor_sync(0xffffffffu, bsum, o);
    }
    float mu = a * (1.f / DD);
    float var = bsum * (1.f / DD) - mu * mu;
    float rstd = rsqrtf(var + 1e-5f);

    float v[16];
    a = 0.f; bsum = 0.f;
#pragma unroll
    for (int e = 0; e < 16; ++e) {
        int c = e * 32 + lane;
        float rn = (x[e] - mu) * rstd * grec[c] + brec[c];
        v[e] = fmaxf(sr[c] + rn, 0.f);
        a += v[e];
        bsum += v[e] * v[e];
    }
#pragma unroll
    for (int o = 16; o; o >>= 1) {
        a += __shfl_xor_sync(0xffffffffu, a, o);
        bsum += __shfl_xor_sync(0xffffffffu, bsum, o);
    }
    float mu2 = a * (1.f / DD);
    float var2 = bsum * (1.f / DD) - mu2 * mu2;
    float rstd2 = rsqrtf(var2 + 1e-5f);
#pragma unroll
    for (int e = 0; e < 16; ++e) {
        int c = e * 32 + lane;
        orow[c] = (v[e] - mu2) * rstd2 * gact[c] + bact[c];
    }
}

// ---------- weight update: out = l2norm_rows(W*(1-decay_i) + alpha_j*(G@W)), both mats ----------
#define RPC 8
__global__ __launch_bounds__(512) void weight_update(const float* __restrict__ W0,
                                                     const float* __restrict__ G0,
                                                     const float* __restrict__ W1,
                                                     const float* __restrict__ G1,
                                                     const float* __restrict__ alpha,
                                                     const float* __restrict__ decay,
                                                     float* __restrict__ out0,
                                                     float* __restrict__ out1) {
    const float* Wm = blockIdx.y ? W1 : W0;
    const float* G = blockIdx.y ? G1 : G0;
    float* outp = blockIdx.y ? out1 : out0;

    const int i0 = blockIdx.x * RPC;
    const int j = threadIdx.x;
    const int lane = j & 31;
    const int w = j >> 5;

    __shared__ float Gsm[RPC][DD];
    __shared__ float red[16];
    __shared__ float norms[RPC];

#pragma unroll
    for (int r = 0; r < RPC; ++r) Gsm[r][j] = G[(size_t)(i0 + r) * DD + j];
    __syncthreads();

    float acc[RPC];
#pragma unroll
    for (int r = 0; r < RPC; ++r) acc[r] = 0.f;

#pragma unroll 4
    for (int k = 0; k < DD; ++k) {
        float wv = Wm[(size_t)k * DD + j];
#pragma unroll
        for (int r = 0; r < RPC; ++r) acc[r] = fmaf(Gsm[r][k], wv, acc[r]);
    }

    float aj = alpha[j];
#pragma unroll
    for (int r = 0; r < RPC; ++r)
        acc[r] = Wm[(size_t)(i0 + r) * DD + j] * (1.f - decay[i0 + r]) + aj * acc[r];

    for (int r = 0; r < RPC; ++r) {
        float s = acc[r] * acc[r];
#pragma unroll
        for (int o = 16; o; o >>= 1) s += __shfl_xor_sync(0xffffffffu, s, o);
        if (lane == 0) red[w] = s;
        __syncthreads();
        if (j == 0) {
            float tsum = 0.f;
#pragma unroll
            for (int q = 0; q < 16; ++q) tsum += red[q];
            norms[r] = fmaxf(sqrtf(tsum), 1e-12f);
        }
        __syncthreads();
    }

#pragma unroll
    for (int r = 0; r < RPC; ++r)
        outp[(size_t)(i0 + r) * DD + j] = acc[r] / norms[r];
}

// ---------------- launch ----------------
extern "C" void kernel_launch(void* const* d_in, const int* in_sizes, int n_in,
                              void* d_out, int out_size) {
    const float* stim = (const float*)d_in[0];
    const float* prev = (const float*)d_in[1];
    const float* W    = (const float*)d_in[2];
    const float* Wr   = (const float*)d_in[3];
    const float* alpha = (const float*)d_in[4];
    const float* decay = (const float*)d_in[5];
    const float* gact = (const float*)d_in[6];
    const float* bact = (const float*)d_in[7];
    const float* grec = (const float*)d_in[8];
    const float* brec = (const float*)d_in[9];
    float* out = (float*)d_out;

    const int Brows = in_sizes[0] / DD;  // 32768

    fp16 *s_hi, *s_lo, *p_hi, *p_lo, *st_hi, *st_lo, *pt_hi, *pt_lo, *wt_hi, *wrt_hi;
    float *stim_out, *rec_out, *partS, *partP, *GS, *GP;
    cudaGetSymbolAddress((void**)&s_hi, g_s_hi);
    cudaGetSymbolAddress((void**)&s_lo, g_s_lo);
    cudaGetSymbolAddress((void**)&p_hi, g_p_hi);
    cudaGetSymbolAddress((void**)&p_lo, g_p_lo);
    cudaGetSymbolAddress((void**)&st_hi, g_st_hi);
    cudaGetSymbolAddress((void**)&st_lo, g_st_lo);
    cudaGetSymbolAddress((void**)&pt_hi, g_pt_hi);
    cudaGetSymbolAddress((void**)&pt_lo, g_pt_lo);
    cudaGetSymbolAddress((void**)&wt_hi, g_wt_hi);
    cudaGetSymbolAddress((void**)&wrt_hi, g_wrt_hi);
    cudaGetSymbolAddress((void**)&stim_out, g_stim_out);
    cudaGetSymbolAddress((void**)&rec_out, g_rec_out);
    cudaGetSymbolAddress((void**)&partS, g_partS);
    cudaGetSymbolAddress((void**)&partP, g_partP);
    cudaGetSymbolAddress((void**)&GS, g_GS);
    cudaGetSymbolAddress((void**)&GP, g_GP);

    cudaFuncSetAttribute(mma_all, cudaFuncAttributeMaxDynamicSharedMemorySize, SMEM_DYN);

    // launches 0-2: prep (mma_all stays at ncu capture index 3)
    prep_big<<<dim3(DD / 64, Brows / 64), 256>>>(stim, (uint32_t*)s_hi, (uint32_t*)s_lo,
                                                 (uint32_t*)st_hi, (uint32_t*)st_lo, Brows, DD);
    prep_big<<<dim3(DD / 64, Brows / 64), 256>>>(prev, (uint32_t*)p_hi, (uint32_t*)p_lo,
                                                 (uint32_t*)pt_hi, (uint32_t*)pt_lo, Brows, DD);
    prep_w<<<dim3(DD / 64, DD / 64, 2), 256>>>(W, Wr, (uint32_t*)wt_hi, (uint32_t*)wrt_hi);

    // launch 3: ALL four GEMMs merged, gram blocks first (LPT order)
    const int fwdBlocks = (Brows / MT) * (DD / NT);   // 2048
    const int gramBlocks = 20 * NSPLIT;               // 320
    const int kcg = Brows / NSPLIT;                   // 2048
    Seg4 segs;
    segs.s[0] = {st_hi, st_lo, st_hi, Brows, Brows, partS, DD * DD, kcg, 1, 0};
    segs.s[1] = {pt_hi, pt_lo, pt_hi, Brows, Brows, partP, DD * DD, kcg, 1, gramBlocks};
    segs.s[2] = {s_hi, s_lo, wt_hi, DD, DD, stim_out, 0, DD, 0, 2 * gramBlocks};
    segs.s[3] = {p_hi, p_lo, wrt_hi, DD, DD, rec_out, 0, DD, 0, 2 * gramBlocks + fwdBlocks};
    mma_all<<<2 * gramBlocks + 2 * fwdBlocks, 256, SMEM_DYN>>>(segs);

    reduce_gram<<<(DD * DD) / 256, 256>>>();

    ln_fuse<<<(unsigned)(Brows / 8), 256>>>(rec_out, stim_out, grec, brec, gact, bact, out);

    size_t off = (size_t)Brows * DD;
    weight_update<<<dim3(DD / RPC, 2), 512>>>(W, GS, Wr, GP, alpha, decay,
                                              out + off, out + off + (size_t)DD * DD);
}

// round 11
// speedup vs baseline: 1.2659x; 1.0456x over previous
#include <cuda_runtime.h>
#include <cuda_fp16.h>
#include <cstdint>

typedef __half fp16;

// ---------------- problem constants ----------------
#define DD 512
#define MAXB 32768
#define NSPLIT 16
#define BKT 64                          // K per stage -> 128B rows
#define MT 128
#define NT 128
#define TILE_A (MT * BKT * 2)           // 16384 B (A hi); A lo same; B hi same
#define STAGE_B (3 * TILE_A)            // 49152 B (Ahi, Alo, Bhi)
#define SMEM_DYN (2 * STAGE_B + 128)    // 98432 B -> 2 CTAs/SM

// ---------------- scratch (device globals; no allocation) ----------------
__device__ __align__(256) fp16 g_s_hi[(size_t)MAXB * DD];
__device__ __align__(256) fp16 g_s_lo[(size_t)MAXB * DD];
__device__ __align__(256) fp16 g_p_hi[(size_t)MAXB * DD];
__device__ __align__(256) fp16 g_p_lo[(size_t)MAXB * DD];
__device__ __align__(256) fp16 g_st_hi[(size_t)DD * MAXB];
__device__ __align__(256) fp16 g_st_lo[(size_t)DD * MAXB];
__device__ __align__(256) fp16 g_pt_hi[(size_t)DD * MAXB];
__device__ __align__(256) fp16 g_pt_lo[(size_t)DD * MAXB];
__device__ __align__(256) fp16 g_wt_hi[DD * DD];
__device__ __align__(256) fp16 g_wrt_hi[DD * DD];
__device__ __align__(256) float g_stim_out[(size_t)MAXB * DD];
__device__ __align__(256) float g_rec_out[(size_t)MAXB * DD];
__device__ __align__(256) float g_partS[(size_t)NSPLIT * DD * DD];
__device__ __align__(256) float g_partP[(size_t)NSPLIT * DD * DD];
__device__ __align__(256) float g_GS[DD * DD];
__device__ __align__(256) float g_GP[DD * DD];

// ---------------- PTX helpers (base-ISA only: sm_80+ safe) ----------------
__device__ __forceinline__ uint32_t smem_u32(const void* p) {
    uint32_t a;
    asm("{ .reg .u64 t; cvta.to.shared.u64 t, %1; cvt.u32.u64 %0, t; }" : "=r"(a) : "l"(p));
    return a;
}
__device__ __forceinline__ void ldsm_x4(uint32_t* r, uint32_t addr) {
    asm volatile("ldmatrix.sync.aligned.m8n8.x4.shared.b16 {%0,%1,%2,%3}, [%4];"
                 : "=r"(r[0]), "=r"(r[1]), "=r"(r[2]), "=r"(r[3]) : "r"(addr));
}
__device__ __forceinline__ void mma16816(float* c, const uint32_t* a, uint32_t b0, uint32_t b1) {
    asm volatile(
        "mma.sync.aligned.m16n8k16.row.col.f32.f16.f16.f32 "
        "{%0,%1,%2,%3}, {%4,%5,%6,%7}, {%8,%9}, {%0,%1,%2,%3};"
        : "+f"(c[0]), "+f"(c[1]), "+f"(c[2]), "+f"(c[3])
        : "r"(a[0]), "r"(a[1]), "r"(a[2]), "r"(a[3]), "r"(b0), "r"(b1));
}
__device__ __forceinline__ void cp16(uint32_t dst, const void* src) {
    asm volatile("cp.async.cg.shared.global [%0], [%1], 16;" :: "r"(dst), "l"(src) : "memory");
}
#define CP_COMMIT() asm volatile("cp.async.commit_group;" ::: "memory")

// swizzled smem byte offset within a tile: 128B rows, 8 x 16B chunks, chunk xor (row&7)
__device__ __forceinline__ uint32_t swz(int row, int chunk) {
    return (uint32_t)(row * 128 + ((chunk ^ (row & 7)) << 4));
}

__device__ __forceinline__ uint32_t pack2h(fp16 a, fp16 b) {
    return (uint32_t)__half_as_ushort(a) | ((uint32_t)__half_as_ushort(b) << 16);
}

// ---------------- segment descriptor for the merged GEMM launch ----------------
struct Seg {
    const fp16 *Ah, *Al, *Bh;
    int lda, ldb;
    float* C;
    int pstride;
    int kc;     // K per block
    int gram;   // 0: forward tiling, 1: upper-tri gram tiling
    int blk0;   // first global block id of this segment
};
struct Seg4 { Seg s[4]; };

// ---------------- merged mma.sync GEMM: all 4 GEMMs in one launch ----------------
// C = A @ B^T with A = Ahi + Alo (fp16 pair), B = Bhi (fp16).
// 128x128 CTA tile, warp tile 32x64, 2 CTAs/SM.
__global__ __launch_bounds__(256, 2)
void mma_all(Seg4 segs) {
    extern __shared__ char smraw[];
    const uint32_t base = (smem_u32(smraw) + 127u) & ~127u;

    const int bid = blockIdx.x;
    int si = (bid >= segs.s[2].blk0) ? ((bid >= segs.s[3].blk0) ? 3 : 2)
                                     : ((bid >= segs.s[1].blk0) ? 1 : 0);
    const Seg sg = segs.s[si];
    const int b = bid - sg.blk0;

    const int tid = threadIdx.x;
    const int lane = tid & 31;
    const int wid = tid >> 5;
    const int wm = wid >> 1;       // 4 warp-rows of 32
    const int wn = wid & 1;        // 2 warp-cols of 64
    const int r15 = lane & 15;
    const int hi4 = lane >> 4;

    int m0, n0, kbase;
    float* C = sg.C;
    if (sg.gram) {
        // 10 upper-tri 128x128 tiles
        const int PI[10] = {0, 0, 0, 0, 1, 1, 1, 2, 2, 3};
        const int PJ[10] = {0, 1, 2, 3, 1, 2, 3, 2, 3, 3};
        int p = b % 10, z = b / 10;
        m0 = PI[p] * MT;
        n0 = PJ[p] * NT;
        kbase = z * sg.kc;
        C += (long)z * sg.pstride;
    } else {
        m0 = (b >> 2) * MT;
        n0 = (b & 3) * NT;
        kbase = 0;
    }
    const int niter = sg.kc / BKT;

    // ---- hoisted loader state (int32 math; pointers advance per stage) ----
    const int rr = tid >> 3;                 // 0..31 base row
    const int cch = tid & 7;                 // chunk index
    const uint32_t dA = (uint32_t)(rr * 128 + ((cch ^ (rr & 7)) << 4));
    const int offA = 32 * sg.lda;
    const int offB = 32 * sg.ldb;
    const fp16* pAh = sg.Ah + (m0 + rr) * sg.lda + cch * 8 + kbase;
    const fp16* pAl = sg.Al + (m0 + rr) * sg.lda + cch * 8 + kbase;
    const fp16* pBh = sg.Bh + (n0 + rr) * sg.ldb + cch * 8 + kbase;

#define LOAD_STAGE(sbase) do {                                                  \
    const uint32_t d0 = (sbase) + dA;                                           \
    _Pragma("unroll") for (int q = 0; q < 4; ++q)                               \
        cp16(d0 + q * 4096, pAh + q * offA);                                    \
    _Pragma("unroll") for (int q = 0; q < 4; ++q)                               \
        cp16(d0 + TILE_A + q * 4096, pAl + q * offA);                           \
    _Pragma("unroll") for (int q = 0; q < 4; ++q)                               \
        cp16(d0 + 2 * TILE_A + q * 4096, pBh + q * offB);                       \
    CP_COMMIT();                                                                \
    pAh += BKT; pAl += BKT; pBh += BKT;                                         \
} while (0)

    float acc[2][8][4];
#pragma unroll
    for (int i = 0; i < 2; ++i)
#pragma unroll
        for (int j = 0; j < 8; ++j)
#pragma unroll
            for (int q = 0; q < 4; ++q) acc[i][j][q] = 0.f;

    // prologue: stage 0
    LOAD_STAGE(base);

    for (int i = 0; i < niter; ++i) {
        asm volatile("cp.async.wait_group 0;" ::: "memory");
        __syncthreads();

        if (i + 1 < niter)
            LOAD_STAGE(base + ((i + 1) & 1) * STAGE_B);

        const uint32_t sb = base + (i & 1) * STAGE_B;
        const uint32_t Ah = sb, Al = sb + TILE_A, Bh = sb + 2 * TILE_A;

#pragma unroll
        for (int ks = 0; ks < 4; ++ks) {
            uint32_t ah[2][4], al[2][4], bh[4][4];
            int ck = 2 * ks + hi4;
#pragma unroll
            for (int mt = 0; mt < 2; ++mt) {
                int row = wm * 32 + mt * 16 + r15;
                ldsm_x4(ah[mt], Ah + swz(row, ck));
                ldsm_x4(al[mt], Al + swz(row, ck));
            }
#pragma unroll
            for (int np = 0; np < 4; ++np) {
                int row = wn * 64 + np * 16 + r15;
                ldsm_x4(bh[np], Bh + swz(row, ck));
            }
#pragma unroll
            for (int mt = 0; mt < 2; ++mt)
#pragma unroll
                for (int nt = 0; nt < 8; ++nt) {
                    int np = nt >> 1, p = nt & 1;
                    mma16816(acc[mt][nt], ah[mt], bh[np][p], bh[np][p + 2]);
                    mma16816(acc[mt][nt], al[mt], bh[np][p], bh[np][p + 2]);
                }
        }
    }

    // epilogue: write fp32 directly from accumulators
#pragma unroll
    for (int mt = 0; mt < 2; ++mt) {
        int row = m0 + wm * 32 + mt * 16 + (lane >> 2);
#pragma unroll
        for (int nt = 0; nt < 8; ++nt) {
            int col = n0 + wn * 64 + nt * 8 + 2 * (lane & 3);
            *(float2*)&C[(long)row * DD + col] = make_float2(acc[mt][nt][0], acc[mt][nt][1]);
            *(float2*)&C[(long)(row + 8) * DD + col] = make_float2(acc[mt][nt][2], acc[mt][nt][3]);
        }
    }
#undef LOAD_STAGE
}

// ------- prep: coalesced fp16 hi/lo split, row-major + transposed, packed stores -------
__global__ __launch_bounds__(256) void prep_big(const float* __restrict__ X,
                                                uint32_t* __restrict__ Hr, uint32_t* __restrict__ Lr,
                                                uint32_t* __restrict__ Th, uint32_t* __restrict__ Tl,
                                                int R, int C) {
    __shared__ float s[64][65];
    const int tid = threadIdx.x;
    const int c0 = blockIdx.x * 64, r0 = blockIdx.y * 64;

#pragma unroll
    for (int k = 0; k < 8; ++k) {
        int u = tid + k * 256;
        int rl = u >> 5, c2 = (u & 31) * 2;
        long ga = (long)(r0 + rl) * C + c0 + c2;
        float2 v = *(const float2*)&X[ga];
        fp16 h0 = __float2half(v.x);
        fp16 l0 = __float2half(v.x - __half2float(h0));
        fp16 h1 = __float2half(v.y);
        fp16 l1 = __float2half(v.y - __half2float(h1));
        Hr[ga >> 1] = pack2h(h0, h1);
        Lr[ga >> 1] = pack2h(l0, l1);
        s[c2][rl] = v.x;
        s[c2 + 1][rl] = v.y;
    }
    __syncthreads();
#pragma unroll
    for (int k = 0; k < 8; ++k) {
        int u = tid + k * 256;
        int fl = u >> 5, r2 = (u & 31) * 2;
        float v0 = s[fl][r2], v1 = s[fl][r2 + 1];
        fp16 h0 = __float2half(v0);
        fp16 l0 = __float2half(v0 - __half2float(h0));
        fp16 h1 = __float2half(v1);
        fp16 l1 = __float2half(v1 - __half2float(h1));
        long ta = (long)(c0 + fl) * R + r0 + r2;
        Th[ta >> 1] = pack2h(h0, h1);
        Tl[ta >> 1] = pack2h(l0, l1);
    }
}

// ------- prep for weights: transposed HI-only (B operand never needs lo) -------
__global__ __launch_bounds__(256) void prep_w(const float* __restrict__ W0,
                                              const float* __restrict__ W1,
                                              uint32_t* __restrict__ T0h,
                                              uint32_t* __restrict__ T1h) {
    __shared__ float s[64][65];
    const int tid = threadIdx.x;
    const int c0 = blockIdx.x * 64, r0 = blockIdx.y * 64;
    const float* X = blockIdx.z ? W1 : W0;
    uint32_t* Th = blockIdx.z ? T1h : T0h;

#pragma unroll
    for (int k = 0; k < 8; ++k) {
        int u = tid + k * 256;
        int rl = u >> 5, c2 = (u & 31) * 2;
        float2 v = *(const float2*)&X[(long)(r0 + rl) * DD + c0 + c2];
        s[c2][rl] = v.x;
        s[c2 + 1][rl] = v.y;
    }
    __syncthreads();
#pragma unroll
    for (int k = 0; k < 8; ++k) {
        int u = tid + k * 256;
        int fl = u >> 5, r2 = (u & 31) * 2;
        fp16 h0 = __float2half(s[fl][r2]);
        fp16 h1 = __float2half(s[fl][r2 + 1]);
        long ta = (long)(c0 + fl) * DD + r0 + r2;
        Th[ta >> 1] = pack2h(h0, h1);
    }
}

// ---------------- reduce split-K Gram partials (symmetric mirror, 128-granular) ----------------
__global__ void reduce_gram() {
    int idx = blockIdx.x * blockDim.x + threadIdx.x;
    int i = idx >> 9, j = idx & 511;
    size_t src = ((i >> 7) <= (j >> 7)) ? ((size_t)i * DD + j) : ((size_t)j * DD + i);
    float s = 0.f, p = 0.f;
#pragma unroll 8
    for (int z = 0; z < NSPLIT; ++z) {
        s += g_partS[(size_t)z * DD * DD + src];
        p += g_partP[(size_t)z * DD * DD + src];
    }
    g_GS[idx] = s;
    g_GP[idx] = p;
}

// ---------------- warp-per-row fused LN(rec) -> add stim -> relu -> LN(act) ----------------
__global__ __launch_bounds__(256) void ln_fuse(const float* __restrict__ rec,
                                               const float* __restrict__ stim,
                                               const float* __restrict__ grec,
                                               const float* __restrict__ brec,
                                               const float* __restrict__ gact,
                                               const float* __restrict__ bact,
                                               float* __restrict__ out) {
    const int lane = threadIdx.x & 31;
    const long row = (long)blockIdx.x * 8 + (threadIdx.x >> 5);
    const float* rr = rec + row * DD;
    const float* sr = stim + row * DD;
    float* orow = out + row * DD;

    float x[16];
    float a = 0.f, bsum = 0.f;
#pragma unroll
    for (int e = 0; e < 16; ++e) {
        x[e] = rr[e * 32 + lane];
        a += x[e];
        bsum += x[e] * x[e];
    }
#pragma unroll
    for (int o = 16; o; o >>= 1) {
        a += __shfl_xor_sync(0xffffffffu, a, o);
        bsum += __shfl_xor_sync(0xffffffffu, bsum, o);
    }
    float mu = a * (1.f / DD);
    float var = bsum * (1.f / DD) - mu * mu;
    float rstd = rsqrtf(var + 1e-5f);

    float v[16];
    a = 0.f; bsum = 0.f;
#pragma unroll
    for (int e = 0; e < 16; ++e) {
        int c = e * 32 + lane;
        float rn = (x[e] - mu) * rstd * grec[c] + brec[c];
        v[e] = fmaxf(sr[c] + rn, 0.f);
        a += v[e];
        bsum += v[e] * v[e];
    }
#pragma unroll
    for (int o = 16; o; o >>= 1) {
        a += __shfl_xor_sync(0xffffffffu, a, o);
        bsum += __shfl_xor_sync(0xffffffffu, bsum, o);
    }
    float mu2 = a * (1.f / DD);
    float var2 = bsum * (1.f / DD) - mu2 * mu2;
    float rstd2 = rsqrtf(var2 + 1e-5f);
#pragma unroll
    for (int e = 0; e < 16; ++e) {
        int c = e * 32 + lane;
        orow[c] = (v[e] - mu2) * rstd2 * gact[c] + bact[c];
    }
}

// ---------- weight update: out = l2norm_rows(W*(1-decay_i) + alpha_j*(G@W)), both mats ----------
#define RPC 8
__global__ __launch_bounds__(512) void weight_update(const float* __restrict__ W0,
                                                     const float* __restrict__ G0,
                                                     const float* __restrict__ W1,
                                                     const float* __restrict__ G1,
                                                     const float* __restrict__ alpha,
                                                     const float* __restrict__ decay,
                                                     float* __restrict__ out0,
                                                     float* __restrict__ out1) {
    const float* Wm = blockIdx.y ? W1 : W0;
    const float* G = blockIdx.y ? G1 : G0;
    float* outp = blockIdx.y ? out1 : out0;

    const int i0 = blockIdx.x * RPC;
    const int j = threadIdx.x;
    const int lane = j & 31;
    const int w = j >> 5;

    __shared__ float Gsm[RPC][DD];
    __shared__ float red[16];
    __shared__ float norms[RPC];

#pragma unroll
    for (int r = 0; r < RPC; ++r) Gsm[r][j] = G[(size_t)(i0 + r) * DD + j];
    __syncthreads();

    float acc[RPC];
#pragma unroll
    for (int r = 0; r < RPC; ++r) acc[r] = 0.f;

#pragma unroll 4
    for (int k = 0; k < DD; ++k) {
        float wv = Wm[(size_t)k * DD + j];
#pragma unroll
        for (int r = 0; r < RPC; ++r) acc[r] = fmaf(Gsm[r][k], wv, acc[r]);
    }

    float aj = alpha[j];
#pragma unroll
    for (int r = 0; r < RPC; ++r)
        acc[r] = Wm[(size_t)(i0 + r) * DD + j] * (1.f - decay[i0 + r]) + aj * acc[r];

    for (int r = 0; r < RPC; ++r) {
        float s = acc[r] * acc[r];
#pragma unroll
        for (int o = 16; o; o >>= 1) s += __shfl_xor_sync(0xffffffffu, s, o);
        if (lane == 0) red[w] = s;
        __syncthreads();
        if (j == 0) {
            float tsum = 0.f;
#pragma unroll
            for (int q = 0; q < 16; ++q) tsum += red[q];
            norms[r] = fmaxf(sqrtf(tsum), 1e-12f);
        }
        __syncthreads();
    }

#pragma unroll
    for (int r = 0; r < RPC; ++r)
        outp[(size_t)(i0 + r) * DD + j] = acc[r] / norms[r];
}

// ---------------- launch ----------------
extern "C" void kernel_launch(void* const* d_in, const int* in_sizes, int n_in,
                              void* d_out, int out_size) {
    const float* stim = (const float*)d_in[0];
    const float* prev = (const float*)d_in[1];
    const float* W    = (const float*)d_in[2];
    const float* Wr   = (const float*)d_in[3];
    const float* alpha = (const float*)d_in[4];
    const float* decay = (const float*)d_in[5];
    const float* gact = (const float*)d_in[6];
    const float* bact = (const float*)d_in[7];
    const float* grec = (const float*)d_in[8];
    const float* brec = (const float*)d_in[9];
    float* out = (float*)d_out;

    const int Brows = in_sizes[0] / DD;  // 32768

    fp16 *s_hi, *s_lo, *p_hi, *p_lo, *st_hi, *st_lo, *pt_hi, *pt_lo, *wt_hi, *wrt_hi;
    float *stim_out, *rec_out, *partS, *partP, *GS, *GP;
    cudaGetSymbolAddress((void**)&s_hi, g_s_hi);
    cudaGetSymbolAddress((void**)&s_lo, g_s_lo);
    cudaGetSymbolAddress((void**)&p_hi, g_p_hi);
    cudaGetSymbolAddress((void**)&p_lo, g_p_lo);
    cudaGetSymbolAddress((void**)&st_hi, g_st_hi);
    cudaGetSymbolAddress((void**)&st_lo, g_st_lo);
    cudaGetSymbolAddress((void**)&pt_hi, g_pt_hi);
    cudaGetSymbolAddress((void**)&pt_lo, g_pt_lo);
    cudaGetSymbolAddress((void**)&wt_hi, g_wt_hi);
    cudaGetSymbolAddress((void**)&wrt_hi, g_wrt_hi);
    cudaGetSymbolAddress((void**)&stim_out, g_stim_out);
    cudaGetSymbolAddress((void**)&rec_out, g_rec_out);
    cudaGetSymbolAddress((void**)&partS, g_partS);
    cudaGetSymbolAddress((void**)&partP, g_partP);
    cudaGetSymbolAddress((void**)&GS, g_GS);
    cudaGetSymbolAddress((void**)&GP, g_GP);

    cudaFuncSetAttribute(mma_all, cudaFuncAttributeMaxDynamicSharedMemorySize, SMEM_DYN);

    // launches 0-2: prep (mma_all stays at ncu capture index 3)
    prep_big<<<dim3(DD / 64, Brows / 64), 256>>>(stim, (uint32_t*)s_hi, (uint32_t*)s_lo,
                                                 (uint32_t*)st_hi, (uint32_t*)st_lo, Brows, DD);
    prep_big<<<dim3(DD / 64, Brows / 64), 256>>>(prev, (uint32_t*)p_hi, (uint32_t*)p_lo,
                                                 (uint32_t*)pt_hi, (uint32_t*)pt_lo, Brows, DD);
    prep_w<<<dim3(DD / 64, DD / 64, 2), 256>>>(W, Wr, (uint32_t*)wt_hi, (uint32_t*)wrt_hi);

    // launch 3: ALL four GEMMs merged, gram blocks first (LPT order)
    const int fwdBlocks = (Brows / MT) * (DD / NT);   // 1024
    const int gramBlocks = 10 * NSPLIT;               // 160
    const int kcg = Brows / NSPLIT;                   // 2048
    Seg4 segs;
    segs.s[0] = {st_hi, st_lo, st_hi, Brows, Brows, partS, DD * DD, kcg, 1, 0};
    segs.s[1] = {pt_hi, pt_lo, pt_hi, Brows, Brows, partP, DD * DD, kcg, 1, gramBlocks};
    segs.s[2] = {s_hi, s_lo, wt_hi, DD, DD, stim_out, 0, DD, 0, 2 * gramBlocks};
    segs.s[3] = {p_hi, p_lo, wrt_hi, DD, DD, rec_out, 0, DD, 0, 2 * gramBlocks + fwdBlocks};
    mma_all<<<2 * gramBlocks + 2 * fwdBlocks, 256, SMEM_DYN>>>(segs);

    reduce_gram<<<(DD * DD) / 256, 256>>>();

    ln_fuse<<<(unsigned)(Brows / 8), 256>>>(rec_out, stim_out, grec, brec, gact, bact, out);

    size_t off = (size_t)Brows * DD;
    weight_update<<<dim3(DD / RPC, 2), 512>>>(W, GS, Wr, GP, alpha, decay,
                                              out + off, out + off + (size_t)DD * DD);
}

// round 12
// speedup vs baseline: 1.8063x; 1.4269x over previous
#include <cuda_runtime.h>
#include <cuda_fp16.h>
#include <cstdint>

typedef __half fp16;

// ---------------- problem constants ----------------
#define DD 512
#define MAXB 32768
#define NSPLIT 16
#define BKT 64                          // K per stage -> 128B rows
#define MT 128
#define NT 128
#define TILE_A (MT * BKT * 2)           // 16384 B per operand tile
#define STAGE_B (2 * TILE_A)            // 32768 B (Ahi, Bhi)
#define NSTAGE 3
#define SMEM_DYN (NSTAGE * STAGE_B + 128)   // 98432 B -> 2 CTAs/SM

// ---------------- scratch (device globals; no allocation) ----------------
__device__ __align__(256) fp16 g_s_hi[(size_t)MAXB * DD];
__device__ __align__(256) fp16 g_p_hi[(size_t)MAXB * DD];
__device__ __align__(256) fp16 g_st_hi[(size_t)DD * MAXB];
__device__ __align__(256) fp16 g_pt_hi[(size_t)DD * MAXB];
__device__ __align__(256) fp16 g_wt_hi[DD * DD];
__device__ __align__(256) fp16 g_wrt_hi[DD * DD];
__device__ __align__(256) float g_stim_out[(size_t)MAXB * DD];
__device__ __align__(256) float g_rec_out[(size_t)MAXB * DD];
__device__ __align__(256) float g_partS[(size_t)NSPLIT * DD * DD];
__device__ __align__(256) float g_partP[(size_t)NSPLIT * DD * DD];
__device__ __align__(256) float g_GS[DD * DD];
__device__ __align__(256) float g_GP[DD * DD];

// ---------------- PTX helpers (base-ISA only: sm_80+ safe) ----------------
__device__ __forceinline__ uint32_t smem_u32(const void* p) {
    uint32_t a;
    asm("{ .reg .u64 t; cvta.to.shared.u64 t, %1; cvt.u32.u64 %0, t; }" : "=r"(a) : "l"(p));
    return a;
}
__device__ __forceinline__ void ldsm_x4(uint32_t* r, uint32_t addr) {
    asm volatile("ldmatrix.sync.aligned.m8n8.x4.shared.b16 {%0,%1,%2,%3}, [%4];"
                 : "=r"(r[0]), "=r"(r[1]), "=r"(r[2]), "=r"(r[3]) : "r"(addr));
}
__device__ __forceinline__ void mma16816(float* c, const uint32_t* a, uint32_t b0, uint32_t b1) {
    asm volatile(
        "mma.sync.aligned.m16n8k16.row.col.f32.f16.f16.f32 "
        "{%0,%1,%2,%3}, {%4,%5,%6,%7}, {%8,%9}, {%0,%1,%2,%3};"
        : "+f"(c[0]), "+f"(c[1]), "+f"(c[2]), "+f"(c[3])
        : "r"(a[0]), "r"(a[1]), "r"(a[2]), "r"(a[3]), "r"(b0), "r"(b1));
}
__device__ __forceinline__ void cp16(uint32_t dst, const void* src) {
    asm volatile("cp.async.cg.shared.global [%0], [%1], 16;" :: "r"(dst), "l"(src) : "memory");
}
#define CP_COMMIT() asm volatile("cp.async.commit_group;" ::: "memory")

// swizzled smem byte offset within a tile: 128B rows, 8 x 16B chunks, chunk xor (row&7)
__device__ __forceinline__ uint32_t swz(int row, int chunk) {
    return (uint32_t)(row * 128 + ((chunk ^ (row & 7)) << 4));
}

__device__ __forceinline__ uint32_t pack2h(fp16 a, fp16 b) {
    return (uint32_t)__half_as_ushort(a) | ((uint32_t)__half_as_ushort(b) << 16);
}

// ---------------- segment descriptor for the merged GEMM launch ----------------
struct Seg {
    const fp16 *Ah, *Bh;
    int lda, ldb;
    float* C;
    int pstride;
    int kc;     // K per block
    int gram;   // 0: forward tiling, 1: upper-tri gram tiling
    int blk0;   // first global block id of this segment
};
struct Seg4 { Seg s[4]; };

// ---------------- merged single-pass fp16 GEMM: all 4 GEMMs in one launch ----------------
// C = A @ B^T, A and B fp16 (round-to-nearest quantized), fp32 accumulate.
// 128x128 CTA tile, warp tile 32x64, 3-stage cp.async pipeline, 2 CTAs/SM.
__global__ __launch_bounds__(256, 2)
void mma_all(Seg4 segs) {
    extern __shared__ char smraw[];
    const uint32_t base = (smem_u32(smraw) + 127u) & ~127u;

    const int bid = blockIdx.x;
    int si = (bid >= segs.s[2].blk0) ? ((bid >= segs.s[3].blk0) ? 3 : 2)
                                     : ((bid >= segs.s[1].blk0) ? 1 : 0);
    const Seg sg = segs.s[si];
    const int b = bid - sg.blk0;

    const int tid = threadIdx.x;
    const int lane = tid & 31;
    const int wid = tid >> 5;
    const int wm = wid >> 1;       // 4 warp-rows of 32
    const int wn = wid & 1;        // 2 warp-cols of 64
    const int r15 = lane & 15;
    const int hi4 = lane >> 4;

    int m0, n0, kbase;
    float* C = sg.C;
    if (sg.gram) {
        const int PI[10] = {0, 0, 0, 0, 1, 1, 1, 2, 2, 3};
        const int PJ[10] = {0, 1, 2, 3, 1, 2, 3, 2, 3, 3};
        int p = b % 10, z = b / 10;
        m0 = PI[p] * MT;
        n0 = PJ[p] * NT;
        kbase = z * sg.kc;
        C += (long)z * sg.pstride;
    } else {
        m0 = (b >> 2) * MT;
        n0 = (b & 3) * NT;
        kbase = 0;
    }
    const int niter = sg.kc / BKT;

    // ---- hoisted loader state (int32 math; pointers advance per stage) ----
    const int rr = tid >> 3;                 // 0..31 base row
    const int cch = tid & 7;                 // chunk index
    const uint32_t dA = (uint32_t)(rr * 128 + ((cch ^ (rr & 7)) << 4));
    const int offA = 32 * sg.lda;
    const int offB = 32 * sg.ldb;
    const fp16* pAh = sg.Ah + (m0 + rr) * sg.lda + cch * 8 + kbase;
    const fp16* pBh = sg.Bh + (n0 + rr) * sg.ldb + cch * 8 + kbase;

#define LOAD_STAGE(sbase) do {                                                  \
    const uint32_t d0 = (sbase) + dA;                                           \
    _Pragma("unroll") for (int q = 0; q < 4; ++q)                               \
        cp16(d0 + q * 4096, pAh + q * offA);                                    \
    _Pragma("unroll") for (int q = 0; q < 4; ++q)                               \
        cp16(d0 + TILE_A + q * 4096, pBh + q * offB);                           \
    CP_COMMIT();                                                                \
    pAh += BKT; pBh += BKT;                                                     \
} while (0)

    float acc[2][8][4];
#pragma unroll
    for (int i = 0; i < 2; ++i)
#pragma unroll
        for (int j = 0; j < 8; ++j)
#pragma unroll
            for (int q = 0; q < 4; ++q) acc[i][j][q] = 0.f;

    // prologue: stages 0 and 1
    LOAD_STAGE(base);
    LOAD_STAGE(base + STAGE_B);

    for (int i = 0; i < niter; ++i) {
        if (i + 1 < niter) asm volatile("cp.async.wait_group 1;" ::: "memory");
        else               asm volatile("cp.async.wait_group 0;" ::: "memory");
        __syncthreads();

        if (i + 2 < niter) {
            int b2 = i + 2;
            b2 = b2 - (b2 / 3) * 3;          // (i+2) % 3
            LOAD_STAGE(base + b2 * STAGE_B);
        }

        int b0 = i - (i / 3) * 3;            // i % 3
        const uint32_t sb = base + b0 * STAGE_B;
        const uint32_t Ah = sb, Bh = sb + TILE_A;

#pragma unroll
        for (int ks = 0; ks < 4; ++ks) {
            uint32_t ah[2][4], bh[4][4];
            int ck = 2 * ks + hi4;
#pragma unroll
            for (int mt = 0; mt < 2; ++mt) {
                int row = wm * 32 + mt * 16 + r15;
                ldsm_x4(ah[mt], Ah + swz(row, ck));
            }
#pragma unroll
            for (int np = 0; np < 4; ++np) {
                int row = wn * 64 + np * 16 + r15;
                ldsm_x4(bh[np], Bh + swz(row, ck));
            }
#pragma unroll
            for (int mt = 0; mt < 2; ++mt)
#pragma unroll
                for (int nt = 0; nt < 8; ++nt) {
                    int np = nt >> 1, p = nt & 1;
                    mma16816(acc[mt][nt], ah[mt], bh[np][p], bh[np][p + 2]);
                }
        }
    }

    // epilogue: write fp32 directly from accumulators
#pragma unroll
    for (int mt = 0; mt < 2; ++mt) {
        int row = m0 + wm * 32 + mt * 16 + (lane >> 2);
#pragma unroll
        for (int nt = 0; nt < 8; ++nt) {
            int col = n0 + wn * 64 + nt * 8 + 2 * (lane & 3);
            *(float2*)&C[(long)row * DD + col] = make_float2(acc[mt][nt][0], acc[mt][nt][1]);
            *(float2*)&C[(long)(row + 8) * DD + col] = make_float2(acc[mt][nt][2], acc[mt][nt][3]);
        }
    }
#undef LOAD_STAGE
}

// ------- prep: coalesced fp16 quantize, row-major + transposed, packed stores -------
__global__ __launch_bounds__(256) void prep_big(const float* __restrict__ X,
                                                uint32_t* __restrict__ Hr,
                                                uint32_t* __restrict__ Th,
                                                int R, int C) {
    __shared__ float s[64][65];
    const int tid = threadIdx.x;
    const int c0 = blockIdx.x * 64, r0 = blockIdx.y * 64;

#pragma unroll
    for (int k = 0; k < 8; ++k) {
        int u = tid + k * 256;
        int rl = u >> 5, c2 = (u & 31) * 2;
        long ga = (long)(r0 + rl) * C + c0 + c2;
        float2 v = *(const float2*)&X[ga];
        Hr[ga >> 1] = pack2h(__float2half(v.x), __float2half(v.y));
        s[c2][rl] = v.x;
        s[c2 + 1][rl] = v.y;
    }
    __syncthreads();
#pragma unroll
    for (int k = 0; k < 8; ++k) {
        int u = tid + k * 256;
        int fl = u >> 5, r2 = (u & 31) * 2;
        long ta = (long)(c0 + fl) * R + r0 + r2;
        Th[ta >> 1] = pack2h(__float2half(s[fl][r2]), __float2half(s[fl][r2 + 1]));
    }
}

// ------- prep for weights: transposed fp16 quantize, W and Wr via grid.z -------
__global__ __launch_bounds__(256) void prep_w(const float* __restrict__ W0,
                                              const float* __restrict__ W1,
                                              uint32_t* __restrict__ T0h,
                                              uint32_t* __restrict__ T1h) {
    __shared__ float s[64][65];
    const int tid = threadIdx.x;
    const int c0 = blockIdx.x * 64, r0 = blockIdx.y * 64;
    const float* X = blockIdx.z ? W1 : W0;
    uint32_t* Th = blockIdx.z ? T1h : T0h;

#pragma unroll
    for (int k = 0; k < 8; ++k) {
        int u = tid + k * 256;
        int rl = u >> 5, c2 = (u & 31) * 2;
        float2 v = *(const float2*)&X[(long)(r0 + rl) * DD + c0 + c2];
        s[c2][rl] = v.x;
        s[c2 + 1][rl] = v.y;
    }
    __syncthreads();
#pragma unroll
    for (int k = 0; k < 8; ++k) {
        int u = tid + k * 256;
        int fl = u >> 5, r2 = (u & 31) * 2;
        long ta = (long)(c0 + fl) * DD + r0 + r2;
        Th[ta >> 1] = pack2h(__float2half(s[fl][r2]), __float2half(s[fl][r2 + 1]));
    }
}

// ---------------- reduce split-K Gram partials (symmetric mirror, 128-granular) ----------------
__global__ void reduce_gram() {
    int idx = blockIdx.x * blockDim.x + threadIdx.x;
    int i = idx >> 9, j = idx & 511;
    size_t src = ((i >> 7) <= (j >> 7)) ? ((size_t)i * DD + j) : ((size_t)j * DD + i);
    float s = 0.f, p = 0.f;
#pragma unroll 8
    for (int z = 0; z < NSPLIT; ++z) {
        s += g_partS[(size_t)z * DD * DD + src];
        p += g_partP[(size_t)z * DD * DD + src];
    }
    g_GS[idx] = s;
    g_GP[idx] = p;
}

// ---------------- warp-per-row fused LN(rec) -> add stim -> relu -> LN(act) ----------------
__global__ __launch_bounds__(256) void ln_fuse(const float* __restrict__ rec,
                                               const float* __restrict__ stim,
                                               const float* __restrict__ grec,
                                               const float* __restrict__ brec,
                                               const float* __restrict__ gact,
                                               const float* __restrict__ bact,
                                               float* __restrict__ out) {
    const int lane = threadIdx.x & 31;
    const long row = (long)blockIdx.x * 8 + (threadIdx.x >> 5);
    const float* rr = rec + row * DD;
    const float* sr = stim + row * DD;
    float* orow = out + row * DD;

    float x[16];
    float a = 0.f, bsum = 0.f;
#pragma unroll
    for (int e = 0; e < 16; ++e) {
        x[e] = rr[e * 32 + lane];
        a += x[e];
        bsum += x[e] * x[e];
    }
#pragma unroll
    for (int o = 16; o; o >>= 1) {
        a += __shfl_xor_sync(0xffffffffu, a, o);
        bsum += __shfl_xor_sync(0xffffffffu, bsum, o);
    }
    float mu = a * (1.f / DD);
    float var = bsum * (1.f / DD) - mu * mu;
    float rstd = rsqrtf(var + 1e-5f);

    float v[16];
    a = 0.f; bsum = 0.f;
#pragma unroll
    for (int e = 0; e < 16; ++e) {
        int c = e * 32 + lane;
        float rn = (x[e] - mu) * rstd * grec[c] + brec[c];
        v[e] = fmaxf(sr[c] + rn, 0.f);
        a += v[e];
        bsum += v[e] * v[e];
    }
#pragma unroll
    for (int o = 16; o; o >>= 1) {
        a += __shfl_xor_sync(0xffffffffu, a, o);
        bsum += __shfl_xor_sync(0xffffffffu, bsum, o);
    }
    float mu2 = a * (1.f / DD);
    float var2 = bsum * (1.f / DD) - mu2 * mu2;
    float rstd2 = rsqrtf(var2 + 1e-5f);
#pragma unroll
    for (int e = 0; e < 16; ++e) {
        int c = e * 32 + lane;
        orow[c] = (v[e] - mu2) * rstd2 * gact[c] + bact[c];
    }
}

// ---------- weight update: out = l2norm_rows(W*(1-decay_i) + alpha_j*(G@W)), both mats ----------
#define RPC 8
__global__ __launch_bounds__(512) void weight_update(const float* __restrict__ W0,
                                                     const float* __restrict__ G0,
                                                     const float* __restrict__ W1,
                                                     const float* __restrict__ G1,
                                                     const float* __restrict__ alpha,
                                                     const float* __restrict__ decay,
                                                     float* __restrict__ out0,
                                                     float* __restrict__ out1) {
    const float* Wm = blockIdx.y ? W1 : W0;
    const float* G = blockIdx.y ? G1 : G0;
    float* outp = blockIdx.y ? out1 : out0;

    const int i0 = blockIdx.x * RPC;
    const int j = threadIdx.x;
    const int lane = j & 31;
    const int w = j >> 5;

    __shared__ float Gsm[RPC][DD];
    __shared__ float red[16];
    __shared__ float norms[RPC];

#pragma unroll
    for (int r = 0; r < RPC; ++r) Gsm[r][j] = G[(size_t)(i0 + r) * DD + j];
    __syncthreads();

    float acc[RPC];
#pragma unroll
    for (int r = 0; r < RPC; ++r) acc[r] = 0.f;

#pragma unroll 4
    for (int k = 0; k < DD; ++k) {
        float wv = Wm[(size_t)k * DD + j];
#pragma unroll
        for (int r = 0; r < RPC; ++r) acc[r] = fmaf(Gsm[r][k], wv, acc[r]);
    }

    float aj = alpha[j];
#pragma unroll
    for (int r = 0; r < RPC; ++r)
        acc[r] = Wm[(size_t)(i0 + r) * DD + j] * (1.f - decay[i0 + r]) + aj * acc[r];

    for (int r = 0; r < RPC; ++r) {
        float s = acc[r] * acc[r];
#pragma unroll
        for (int o = 16; o; o >>= 1) s += __shfl_xor_sync(0xffffffffu, s, o);
        if (lane == 0) red[w] = s;
        __syncthreads();
        if (j == 0) {
            float tsum = 0.f;
#pragma unroll
            for (int q = 0; q < 16; ++q) tsum += red[q];
            norms[r] = fmaxf(sqrtf(tsum), 1e-12f);
        }
        __syncthreads();
    }

#pragma unroll
    for (int r = 0; r < RPC; ++r)
        outp[(size_t)(i0 + r) * DD + j] = acc[r] / norms[r];
}

// ---------------- launch ----------------
extern "C" void kernel_launch(void* const* d_in, const int* in_sizes, int n_in,
                              void* d_out, int out_size) {
    const float* stim = (const float*)d_in[0];
    const float* prev = (const float*)d_in[1];
    const float* W    = (const float*)d_in[2];
    const float* Wr   = (const float*)d_in[3];
    const float* alpha = (const float*)d_in[4];
    const float* decay = (const float*)d_in[5];
    const float* gact = (const float*)d_in[6];
    const float* bact = (const float*)d_in[7];
    const float* grec = (const float*)d_in[8];
    const float* brec = (const float*)d_in[9];
    float* out = (float*)d_out;

    const int Brows = in_sizes[0] / DD;  // 32768

    fp16 *s_hi, *p_hi, *st_hi, *pt_hi, *wt_hi, *wrt_hi;
    float *stim_out, *rec_out, *partS, *partP, *GS, *GP;
    cudaGetSymbolAddress((void**)&s_hi, g_s_hi);
    cudaGetSymbolAddress((void**)&p_hi, g_p_hi);
    cudaGetSymbolAddress((void**)&st_hi, g_st_hi);
    cudaGetSymbolAddress((void**)&pt_hi, g_pt_hi);
    cudaGetSymbolAddress((void**)&wt_hi, g_wt_hi);
    cudaGetSymbolAddress((void**)&wrt_hi, g_wrt_hi);
    cudaGetSymbolAddress((void**)&stim_out, g_stim_out);
    cudaGetSymbolAddress((void**)&rec_out, g_rec_out);
    cudaGetSymbolAddress((void**)&partS, g_partS);
    cudaGetSymbolAddress((void**)&partP, g_partP);
    cudaGetSymbolAddress((void**)&GS, g_GS);
    cudaGetSymbolAddress((void**)&GP, g_GP);

    cudaFuncSetAttribute(mma_all, cudaFuncAttributeMaxDynamicSharedMemorySize, SMEM_DYN);

    // launches 0-2: prep (mma_all stays at ncu capture index 3)
    prep_big<<<dim3(DD / 64, Brows / 64), 256>>>(stim, (uint32_t*)s_hi, (uint32_t*)st_hi, Brows, DD);
    prep_big<<<dim3(DD / 64, Brows / 64), 256>>>(prev, (uint32_t*)p_hi, (uint32_t*)pt_hi, Brows, DD);
    prep_w<<<dim3(DD / 64, DD / 64, 2), 256>>>(W, Wr, (uint32_t*)wt_hi, (uint32_t*)wrt_hi);

    // launch 3: ALL four GEMMs merged, gram blocks first (LPT order)
    const int fwdBlocks = (Brows / MT) * (DD / NT);   // 1024
    const int gramBlocks = 10 * NSPLIT;               // 160
    const int kcg = Brows / NSPLIT;                   // 2048
    Seg4 segs;
    segs.s[0] = {st_hi, st_hi, Brows, Brows, partS, DD * DD, kcg, 1, 0};
    segs.s[1] = {pt_hi, pt_hi, Brows, Brows, partP, DD * DD, kcg, 1, gramBlocks};
    segs.s[2] = {s_hi, wt_hi, DD, DD, stim_out, 0, DD, 0, 2 * gramBlocks};
    segs.s[3] = {p_hi, wrt_hi, DD, DD, rec_out, 0, DD, 0, 2 * gramBlocks + fwdBlocks};
    mma_all<<<2 * gramBlocks + 2 * fwdBlocks, 256, SMEM_DYN>>>(segs);

    reduce_gram<<<(DD * DD) / 256, 256>>>();

    ln_fuse<<<(unsigned)(Brows / 8), 256>>>(rec_out, stim_out, grec, brec, gact, bact, out);

    size_t off = (size_t)Brows * DD;
    weight_update<<<dim3(DD / RPC, 2), 512>>>(W, GS, Wr, GP, alpha, decay,
                                              out + off, out + off + (size_t)DD * DD);
}